// round 3
// baseline (speedup 1.0000x reference)
#include <cuda_runtime.h>
#include <math.h>

#define T_LEN 1024
#define B_SZ  64
#define H_SZ  256
#define D_SZ  256
#define C4    1024          // 4*H, gate-major-within-neuron: col = j*4 + k
#define NCTA  128

// ---------------- scratch (static device allocations only) ----------------
__device__ float g_M2[D_SZ * C4];            // 1 MB   x-projection matrix
__device__ float g_bias2[C4];
__device__ float g_Wp[H_SZ * C4];            // 1 MB   recurrent matrix (Wh - We)
__device__ float g_Z[(size_t)B_SZ * T_LEN * C4];   // 256 MB precomputed input gates
__device__ float g_hT[2][H_SZ * B_SZ];       // transposed h state, double buffered
__device__ unsigned g_count;                 // grid barrier
__device__ unsigned g_epoch;

// ---------------- phase 0a: M2[d][j*4+k] = Wx[k][d][j] + sum_e W_in[d][e]*We[k][e][j]
__global__ void k_prepM(const float* __restrict__ Win, const float* __restrict__ Wx,
                        const float* __restrict__ We, const float* __restrict__ b) {
    int k = blockIdx.x;          // 0..3
    int d = blockIdx.y;          // 0..255
    int j = threadIdx.x;         // 0..255
    float acc = Wx[(k * D_SZ + d) * H_SZ + j];
    const float* wrow = &Win[d * H_SZ];
#pragma unroll 8
    for (int e = 0; e < H_SZ; e++)
        acc = fmaf(__ldg(&wrow[e]), __ldg(&We[(k * H_SZ + e) * H_SZ + j]), acc);
    g_M2[d * C4 + j * 4 + k] = acc;
    if (d == 0) g_bias2[j * 4 + k] = b[k * H_SZ + j];
}

// ---------------- phase 0b: Wp[h][j*4+k] = Wh[k][h][j] - We[k][h][j]
__global__ void k_prepW(const float* __restrict__ Wh, const float* __restrict__ We) {
    int k = blockIdx.x, h = blockIdx.y, j = threadIdx.x;
    int src = (k * H_SZ + h) * H_SZ + j;
    g_Wp[h * C4 + j * 4 + k] = Wh[src] - We[src];
}

// ---------------- tiled fp32 GEMM with bias:  C[M][N] = A[M][K] * B[K][N] + bias[N]
// Block tile: 128 (M) x BN=64 (N), 256 threads, each computes 8x4.
template<int BN>
__global__ void __launch_bounds__(256) k_gemm_bias(
    const float* __restrict__ A, const float* __restrict__ Bm,
    const float* __restrict__ bias, float* __restrict__ Cm,
    int N, int K)
{
    const int BM = 128, BK = 16, TM = 8, TN = 4;
    __shared__ float As[BK][BM + 4];
    __shared__ float Bs[BK][BN + 4];

    int tid = threadIdx.x;                 // 256 threads
    int tx = tid % (BN / TN);              // BN/4 = 16 cols of threads
    int ty = tid / (BN / TN);              // 16 rows of threads
    int row0 = blockIdx.y * BM;
    int col0 = blockIdx.x * BN;

    float acc[TM][TN];
#pragma unroll
    for (int m = 0; m < TM; m++)
#pragma unroll
        for (int n = 0; n < TN; n++) acc[m][n] = 0.f;

    for (int k0 = 0; k0 < K; k0 += BK) {
        // A tile: BM x BK, stored transposed into As[k][m]
#pragma unroll
        for (int i = tid; i < BM * (BK / 4); i += 256) {
            int r  = i >> 2;       // 0..127
            int c4 = i & 3;        // 0..3
            float4 v = *(const float4*)&A[(size_t)(row0 + r) * K + k0 + c4 * 4];
            As[c4 * 4 + 0][r] = v.x;
            As[c4 * 4 + 1][r] = v.y;
            As[c4 * 4 + 2][r] = v.z;
            As[c4 * 4 + 3][r] = v.w;
        }
        // B tile: BK x BN
#pragma unroll
        for (int i = tid; i < BK * (BN / 4); i += 256) {
            int r  = i / (BN / 4);
            int c4 = i % (BN / 4);
            *(float4*)&Bs[r][c4 * 4] =
                *(const float4*)&Bm[(size_t)(k0 + r) * N + col0 + c4 * 4];
        }
        __syncthreads();

#pragma unroll
        for (int k = 0; k < BK; k++) {
            float a[TM], bb[TN];
#pragma unroll
            for (int m = 0; m < TM; m++) a[m] = As[k][ty * TM + m];
#pragma unroll
            for (int n = 0; n < TN; n++) bb[n] = Bs[k][tx * TN + n];
#pragma unroll
            for (int m = 0; m < TM; m++)
#pragma unroll
                for (int n = 0; n < TN; n++)
                    acc[m][n] = fmaf(a[m], bb[n], acc[m][n]);
        }
        __syncthreads();
    }

    float4 bv = *(const float4*)&bias[col0 + tx * TN];
#pragma unroll
    for (int m = 0; m < TM; m++) {
        int r = row0 + ty * TM + m;
        float4 o;
        o.x = acc[m][0] + bv.x;
        o.y = acc[m][1] + bv.y;
        o.z = acc[m][2] + bv.z;
        o.w = acc[m][3] + bv.w;
        *(float4*)&Cm[(size_t)r * N + col0 + tx * TN] = o;
    }
}

// ---------------- phase B: persistent recurrent kernel -------------------
// 128 CTAs, each owns 2 neurons (8 gate columns). h state stored transposed
// in global ([H][B]), double buffered; c state lives in registers of the
// 128 "gate threads" of the owning CTA. One software grid barrier per step.
#define GRIDBAR()                                                          \
    do {                                                                   \
        __syncthreads();                                                   \
        nbar++;                                                            \
        if (tid == 0) {                                                    \
            __threadfence();                                               \
            unsigned prev = atomicAdd(&g_count, 1);                        \
            if (prev == NCTA - 1) {                                        \
                atomicExch(&g_count, 0);                                   \
                __threadfence();                                           \
                *(volatile unsigned*)&g_epoch = base + nbar;               \
            } else {                                                       \
                while ((*(volatile unsigned*)&g_epoch) - base < nbar) { }  \
            }                                                              \
            __threadfence();                                               \
        }                                                                  \
        __syncthreads();                                                   \
    } while (0)

__global__ void __launch_bounds__(256, 1) k_recur(
    const float* __restrict__ h_prev, const float* __restrict__ c_prev,
    float* __restrict__ hseq, float* __restrict__ cseq)
{
    extern __shared__ float sm[];
    float* hs = sm;                 // 16384 floats: h transposed [d][b]
    float* ws = sm + 16384;         //  2048 floats: Wp slice [d][8]
    float* pp = sm + 18432;         //  4608 floats: partials [ks][b][9]

    const int tid = threadIdx.x;
    const int cta = blockIdx.x;

    // stage this CTA's 8 recurrent-weight columns (constant across steps)
    for (int i = tid; i < H_SZ * 8; i += 256)
        ws[i] = g_Wp[(i >> 3) * C4 + cta * 8 + (i & 7)];

    // initialize the transposed h state (each CTA writes its 2 rows)
    for (int i = tid; i < 2 * B_SZ; i += 256) {
        int jl = i >> 6, bb = i & 63;
        g_hT[0][(cta * 2 + jl) * B_SZ + bb] = h_prev[bb * H_SZ + cta * 2 + jl];
    }

    // gate threads (tid < 128) own one (b, local-neuron) pair; c in register
    const int gb  = tid >> 1;
    const int gjl = tid & 1;
    const int gjg = cta * 2 + gjl;
    float creg = 0.f;
    if (tid < 128) creg = c_prev[gb * H_SZ + gjg];

    // compute mapping: 8-way K split, 4b x 4col register tiles
    const int q  = tid & 31;
    const int ks = tid >> 5;       // 0..7  -> d range [ks*32, ks*32+32)
    const int bq = q & 15;         // 0..15 -> b = 4*bq..4*bq+3
    const int ch = q >> 4;         // 0..1  -> cols 4*ch..4*ch+3
    const int d0 = ks * 32;

    unsigned base;
    {
        __shared__ unsigned sb;
        if (tid == 0) sb = *(volatile unsigned*)&g_epoch;
        __syncthreads();
        base = sb;
    }
    unsigned nbar = 0;

    GRIDBAR();   // hT init visible everywhere

    for (int t = 0; t < T_LEN; t++) {
        const int par = t & 1;

        // stage h (bypass L1: written by other CTAs last step)
        const float4* src = (const float4*)&g_hT[par][0];
        float4* dst = (float4*)hs;
#pragma unroll
        for (int i = 0; i < 16; i++)
            dst[tid + i * 256] = __ldcg(&src[tid + i * 256]);
        __syncthreads();

        // partial GEMM: acc[col][b] over this thread's 32 d's
        float4 a0 = {0.f,0.f,0.f,0.f}, a1 = a0, a2 = a0, a3 = a0;
#pragma unroll 8
        for (int dd = 0; dd < 32; dd++) {
            int d = d0 + dd;
            float4 hb = *(const float4*)&hs[d * B_SZ + bq * 4];
            float4 wv = *(const float4*)&ws[d * 8 + ch * 4];
            a0.x = fmaf(hb.x, wv.x, a0.x); a0.y = fmaf(hb.y, wv.x, a0.y);
            a0.z = fmaf(hb.z, wv.x, a0.z); a0.w = fmaf(hb.w, wv.x, a0.w);
            a1.x = fmaf(hb.x, wv.y, a1.x); a1.y = fmaf(hb.y, wv.y, a1.y);
            a1.z = fmaf(hb.z, wv.y, a1.z); a1.w = fmaf(hb.w, wv.y, a1.w);
            a2.x = fmaf(hb.x, wv.z, a2.x); a2.y = fmaf(hb.y, wv.z, a2.y);
            a2.z = fmaf(hb.z, wv.z, a2.z); a2.w = fmaf(hb.w, wv.z, a2.w);
            a3.x = fmaf(hb.x, wv.w, a3.x); a3.y = fmaf(hb.y, wv.w, a3.y);
            a3.z = fmaf(hb.z, wv.w, a3.z); a3.w = fmaf(hb.w, wv.w, a3.w);
        }
        {
            int c0 = ch * 4;
            int base_row = ks * 64 + bq * 4;
            pp[(base_row + 0) * 9 + c0 + 0] = a0.x;
            pp[(base_row + 1) * 9 + c0 + 0] = a0.y;
            pp[(base_row + 2) * 9 + c0 + 0] = a0.z;
            pp[(base_row + 3) * 9 + c0 + 0] = a0.w;
            pp[(base_row + 0) * 9 + c0 + 1] = a1.x;
            pp[(base_row + 1) * 9 + c0 + 1] = a1.y;
            pp[(base_row + 2) * 9 + c0 + 1] = a1.z;
            pp[(base_row + 3) * 9 + c0 + 1] = a1.w;
            pp[(base_row + 0) * 9 + c0 + 2] = a2.x;
            pp[(base_row + 1) * 9 + c0 + 2] = a2.y;
            pp[(base_row + 2) * 9 + c0 + 2] = a2.z;
            pp[(base_row + 3) * 9 + c0 + 2] = a2.w;
            pp[(base_row + 0) * 9 + c0 + 3] = a3.x;
            pp[(base_row + 1) * 9 + c0 + 3] = a3.y;
            pp[(base_row + 2) * 9 + c0 + 3] = a3.z;
            pp[(base_row + 3) * 9 + c0 + 3] = a3.w;
        }
        __syncthreads();

        if (tid < 128) {
            float p0 = 0.f, p1 = 0.f, p2 = 0.f, p3 = 0.f;
#pragma unroll
            for (int s = 0; s < 8; s++) {
                const float* row = &pp[(s * 64 + gb) * 9 + gjl * 4];
                p0 += row[0]; p1 += row[1]; p2 += row[2]; p3 += row[3];
            }
            const float4 z = *(const float4*)
                &g_Z[(size_t)(gb * T_LEN + t) * C4 + gjg * 4];
            p0 += z.x; p1 += z.y; p2 += z.z; p3 += z.w;

            float f  = 1.f / (1.f + expf(-p0));
            float ig = 1.f / (1.f + expf(-p1));
            float o  = 1.f / (1.f + expf(-p2));
            float g  = tanhf(p3);
            creg = f * creg + ig * g;
            float hn = o * tanhf(creg);

            g_hT[par ^ 1][gjg * B_SZ + gb] = hn;
            size_t off = (size_t)(gb * T_LEN + t) * H_SZ + gjg;
            hseq[off] = hn;
            cseq[off] = creg;
            __threadfence();
        }
        GRIDBAR();
    }
}

// ---------------- launch --------------------------------------------------
extern "C" void kernel_launch(void* const* d_in, const int* in_sizes, int n_in,
                              void* d_out, int out_size) {
    const float* x    = (const float*)d_in[0];   // [B,T,D]
    const float* h0   = (const float*)d_in[1];   // [B,H]
    const float* c0   = (const float*)d_in[2];   // [B,H]
    const float* Win  = (const float*)d_in[3];   // [D,H]
    const float* Wx   = (const float*)d_in[4];   // [4,D,H]
    const float* Wh   = (const float*)d_in[5];   // [4,H,H]
    const float* We   = (const float*)d_in[6];   // [4,H,H]
    const float* bb   = (const float*)d_in[7];   // [4,H]
    const float* Wout = (const float*)d_in[8];   // [H,D]
    const float* bout = (const float*)d_in[9];   // [D]

    float* out  = (float*)d_out;
    float* yhat = out;                                   // [B,T,D]
    float* hseq = out + (size_t)B_SZ * T_LEN * D_SZ;     // [B,T,H]
    float* cseq = hseq + (size_t)B_SZ * T_LEN * H_SZ;    // [B,T,H]

    float *pM2, *pbias2, *pZ;
    cudaGetSymbolAddress((void**)&pM2,    g_M2);
    cudaGetSymbolAddress((void**)&pbias2, g_bias2);
    cudaGetSymbolAddress((void**)&pZ,     g_Z);

    // phase 0: fold weights
    k_prepM<<<dim3(4, 256), 256>>>(Win, Wx, We, bb);
    k_prepW<<<dim3(4, 256), 256>>>(Wh, We);

    // phase A: Z = x * M2 + bias2      (65536 x 1024 x 256), 64-wide tiles
    k_gemm_bias<64><<<dim3(1024 / 64, 65536 / 128), 256>>>(
        x, pM2, pbias2, pZ, 1024, 256);

    // phase B: serial recurrence (persistent, grid-barriered)
    cudaFuncSetAttribute(k_recur, cudaFuncAttributeMaxDynamicSharedMemorySize,
                         92160);
    k_recur<<<NCTA, 256, 92160>>>(h0, c0, hseq, cseq);

    // phase C: y = h_seq * W_out + b_out   (65536 x 256 x 256), 64-wide tiles
    k_gemm_bias<64><<<dim3(256 / 64, 65536 / 128), 256>>>(
        hseq, Wout, bout, yhat, 256, 256);
}

// round 4
// speedup vs baseline: 1.1607x; 1.1607x over previous
#include <cuda_runtime.h>
#include <math.h>

#define T_LEN 1024
#define B_SZ  64
#define H_SZ  256
#define D_SZ  256
#define C4    1024          // 4*H, gate-major-within-neuron: col = j*4 + k
#define NCTA  128
#define HS_STRIDE 72        // padded word stride for hs[d][b] (64 + 8)

// ---------------- scratch (static device allocations only) ----------------
__device__ float g_M2[D_SZ * C4];            // 1 MB   x-projection matrix
__device__ float g_bias2[C4];
__device__ float g_Wp[H_SZ * C4];            // 1 MB   recurrent matrix (Wh - We)
__device__ float g_Z[(size_t)B_SZ * T_LEN * C4];   // 256 MB precomputed input gates
__device__ float g_hT[2][H_SZ * B_SZ];       // transposed h state [j][b], double buffered
__device__ unsigned g_count;                 // grid barrier
__device__ unsigned g_epoch;

// ---------------- tf32 mma helpers ----------------------------------------
__device__ __forceinline__ unsigned f2tf32(float x) {
    unsigned r;
    asm("cvt.rna.tf32.f32 %0, %1;" : "=r"(r) : "f"(x));
    return r;
}
__device__ __forceinline__ void mma_tf32(float* c, const unsigned* a, const unsigned* b) {
    asm volatile(
        "mma.sync.aligned.m16n8k8.row.col.f32.tf32.tf32.f32 "
        "{%0,%1,%2,%3}, {%4,%5,%6,%7}, {%8,%9}, {%0,%1,%2,%3};"
        : "+f"(c[0]), "+f"(c[1]), "+f"(c[2]), "+f"(c[3])
        : "r"(a[0]), "r"(a[1]), "r"(a[2]), "r"(a[3]), "r"(b[0]), "r"(b[1]));
}

// ---------------- phase 0a: M2[d][j*4+k] = Wx[k][d][j] + sum_e W_in[d][e]*We[k][e][j]
__global__ void k_prepM(const float* __restrict__ Win, const float* __restrict__ Wx,
                        const float* __restrict__ We, const float* __restrict__ b) {
    int k = blockIdx.x;          // 0..3
    int d = blockIdx.y;          // 0..255
    int j = threadIdx.x;         // 0..255
    float acc = Wx[(k * D_SZ + d) * H_SZ + j];
    const float* wrow = &Win[d * H_SZ];
#pragma unroll 8
    for (int e = 0; e < H_SZ; e++)
        acc = fmaf(__ldg(&wrow[e]), __ldg(&We[(k * H_SZ + e) * H_SZ + j]), acc);
    g_M2[d * C4 + j * 4 + k] = acc;
    if (d == 0) g_bias2[j * 4 + k] = b[k * H_SZ + j];
}

// ---------------- phase 0b: Wp[h][j*4+k] = Wh[k][h][j] - We[k][h][j]
__global__ void k_prepW(const float* __restrict__ Wh, const float* __restrict__ We) {
    int k = blockIdx.x, h = blockIdx.y, j = threadIdx.x;
    int src = (k * H_SZ + h) * H_SZ + j;
    g_Wp[h * C4 + j * 4 + k] = Wh[src] - We[src];
}

// ---------------- tiled fp32 GEMM with bias:  C[M][N] = A[M][K] * B[K][N] + bias[N]
// Block tile: 128 (M) x BN=64 (N), 256 threads, each computes 8x4.
template<int BN>
__global__ void __launch_bounds__(256) k_gemm_bias(
    const float* __restrict__ A, const float* __restrict__ Bm,
    const float* __restrict__ bias, float* __restrict__ Cm,
    int N, int K)
{
    const int BM = 128, BK = 16, TM = 8, TN = 4;
    __shared__ float As[BK][BM + 4];
    __shared__ float Bs[BK][BN + 4];

    int tid = threadIdx.x;                 // 256 threads
    int tx = tid % (BN / TN);              // 16 cols of threads
    int ty = tid / (BN / TN);              // 16 rows of threads
    int row0 = blockIdx.y * BM;
    int col0 = blockIdx.x * BN;

    float acc[TM][TN];
#pragma unroll
    for (int m = 0; m < TM; m++)
#pragma unroll
        for (int n = 0; n < TN; n++) acc[m][n] = 0.f;

    for (int k0 = 0; k0 < K; k0 += BK) {
#pragma unroll
        for (int i = tid; i < BM * (BK / 4); i += 256) {
            int r  = i >> 2;
            int c4 = i & 3;
            float4 v = *(const float4*)&A[(size_t)(row0 + r) * K + k0 + c4 * 4];
            As[c4 * 4 + 0][r] = v.x;
            As[c4 * 4 + 1][r] = v.y;
            As[c4 * 4 + 2][r] = v.z;
            As[c4 * 4 + 3][r] = v.w;
        }
#pragma unroll
        for (int i = tid; i < BK * (BN / 4); i += 256) {
            int r  = i / (BN / 4);
            int c4 = i % (BN / 4);
            *(float4*)&Bs[r][c4 * 4] =
                *(const float4*)&Bm[(size_t)(k0 + r) * N + col0 + c4 * 4];
        }
        __syncthreads();

#pragma unroll
        for (int k = 0; k < BK; k++) {
            float a[TM], bb[TN];
#pragma unroll
            for (int m = 0; m < TM; m++) a[m] = As[k][ty * TM + m];
#pragma unroll
            for (int n = 0; n < TN; n++) bb[n] = Bs[k][tx * TN + n];
#pragma unroll
            for (int m = 0; m < TM; m++)
#pragma unroll
                for (int n = 0; n < TN; n++)
                    acc[m][n] = fmaf(a[m], bb[n], acc[m][n]);
        }
        __syncthreads();
    }

    float4 bv = *(const float4*)&bias[col0 + tx * TN];
#pragma unroll
    for (int m = 0; m < TM; m++) {
        int r = row0 + ty * TM + m;
        float4 o;
        o.x = acc[m][0] + bv.x;
        o.y = acc[m][1] + bv.y;
        o.z = acc[m][2] + bv.z;
        o.w = acc[m][3] + bv.w;
        *(float4*)&Cm[(size_t)r * N + col0 + tx * TN] = o;
    }
}

// ---------------- phase B: persistent recurrent kernel (tf32 mma) ---------
// 128 CTAs, each owns 2 neurons (8 gate columns). Per step each CTA computes
// P[64b x 8col] = h[64 x 256] * Wp[256 x 8] with mma.sync m16n8k8 tf32.
// 8 warps = (4 m-tiles) x (2 k-halves). Wp B-fragments live in registers for
// the whole kernel. h staged [d][b] in smem (stride 72, conflict-free frags).
#define GRIDBAR()                                                          \
    do {                                                                   \
        __syncthreads();                                                   \
        nbar++;                                                            \
        if (tid == 0) {                                                    \
            __threadfence();                                               \
            unsigned prev = atomicAdd(&g_count, 1);                        \
            if (prev == NCTA - 1) {                                        \
                atomicExch(&g_count, 0);                                   \
                __threadfence();                                           \
                *(volatile unsigned*)&g_epoch = base + nbar;               \
            } else {                                                       \
                while ((*(volatile unsigned*)&g_epoch) - base < nbar) { }  \
            }                                                              \
            __threadfence();                                               \
        }                                                                  \
        __syncthreads();                                                   \
    } while (0)

__global__ void __launch_bounds__(256, 1) k_recur(
    const float* __restrict__ h_prev, const float* __restrict__ c_prev,
    float* __restrict__ hseq, float* __restrict__ cseq)
{
    extern __shared__ float sm[];
    float* hs = sm;                           // 256*72 words: h as tf32 [d][b]
    float* pp = sm + H_SZ * HS_STRIDE;        // 2 * 64*12 words: k-half partials

    const int tid  = threadIdx.x;
    const int cta  = blockIdx.x;
    const int lane = tid & 31;
    const int w    = tid >> 5;
    const int mt   = w & 3;                   // m-tile: batches [mt*16, mt*16+16)
    const int kh   = w >> 2;                  // k-half: d in [kh*128, kh*128+128)
    const int b0   = mt * 16;
    const int dbase = kh * 128;
    const int lq = lane >> 2;                 // 0..7
    const int lr = lane & 3;                  // 0..3

    // ---- preload Wp B-fragments into registers (constant across steps) ----
    // B[k][n] col-major frag: b0reg: k=lr, n=lq ; b1reg: k=lr+4
    unsigned bf0[16], bf1[16];
#pragma unroll
    for (int ks = 0; ks < 16; ks++) {
        int d = dbase + ks * 8;
        bf0[ks] = f2tf32(g_Wp[(d + lr)     * C4 + cta * 8 + lq]);
        bf1[ks] = f2tf32(g_Wp[(d + 4 + lr) * C4 + cta * 8 + lq]);
    }

    // initialize the transposed h state (each CTA writes its 2 rows)
    for (int i = tid; i < 2 * B_SZ; i += 256) {
        int jl = i >> 6, bb = i & 63;
        g_hT[0][(cta * 2 + jl) * B_SZ + bb] = h_prev[bb * H_SZ + cta * 2 + jl];
    }

    // gate threads (tid < 128) own one (b, local-neuron) pair; c in register
    const int gb  = tid >> 1;
    const int gjl = tid & 1;
    const int gjg = cta * 2 + gjl;
    float creg = 0.f;
    if (tid < 128) creg = c_prev[gb * H_SZ + gjg];

    unsigned base;
    {
        __shared__ unsigned sb;
        if (tid == 0) sb = *(volatile unsigned*)&g_epoch;
        __syncthreads();
        base = sb;
    }
    unsigned nbar = 0;

    GRIDBAR();   // hT init visible everywhere

    for (int t = 0; t < T_LEN; t++) {
        const int par = t & 1;

        // prefetch this thread's Z (gate threads), overlaps with staging
        float4 z = make_float4(0.f, 0.f, 0.f, 0.f);
        if (tid < 128)
            z = *(const float4*)&g_Z[(size_t)(gb * T_LEN + t) * C4 + gjg * 4];

        // stage h [d][b] into smem, rounding to tf32 (bypass L1: remote writes)
        const float4* src = (const float4*)&g_hT[par][0];
#pragma unroll
        for (int i = 0; i < 16; i++) {
            int f4  = tid + i * 256;          // 0..4095
            float4 v = __ldcg(&src[f4]);
            int row = f4 >> 4;                // d
            int col = (f4 & 15) * 4;          // b
            float* dst = &hs[row * HS_STRIDE + col];
            dst[0] = __uint_as_float(f2tf32(v.x));
            dst[1] = __uint_as_float(f2tf32(v.y));
            dst[2] = __uint_as_float(f2tf32(v.z));
            dst[3] = __uint_as_float(f2tf32(v.w));
        }
        __syncthreads();

        // mma over this warp's k-half, two interleaved acc chains
        float acc0[4] = {0.f, 0.f, 0.f, 0.f};
        float acc1[4] = {0.f, 0.f, 0.f, 0.f};
#pragma unroll
        for (int ks = 0; ks < 16; ks += 2) {
            unsigned a[4];
            {
                int d = dbase + ks * 8;
                const float* p = &hs[(d + lr) * HS_STRIDE + b0 + lq];
                a[0] = __float_as_uint(p[0]);
                a[1] = __float_as_uint(p[8]);
                a[2] = __float_as_uint(p[4 * HS_STRIDE]);
                a[3] = __float_as_uint(p[4 * HS_STRIDE + 8]);
                unsigned bb[2] = {bf0[ks], bf1[ks]};
                mma_tf32(acc0, a, bb);
            }
            {
                int d = dbase + (ks + 1) * 8;
                const float* p = &hs[(d + lr) * HS_STRIDE + b0 + lq];
                a[0] = __float_as_uint(p[0]);
                a[1] = __float_as_uint(p[8]);
                a[2] = __float_as_uint(p[4 * HS_STRIDE]);
                a[3] = __float_as_uint(p[4 * HS_STRIDE + 8]);
                unsigned bb[2] = {bf0[ks + 1], bf1[ks + 1]};
                mma_tf32(acc1, a, bb);
            }
        }
        acc0[0] += acc1[0]; acc0[1] += acc1[1];
        acc0[2] += acc1[2]; acc0[3] += acc1[3];

        // write partials: C frag c0,c1 -> row (b0+lq), cols 2*lr, 2*lr+1
        {
            float* ppk = pp + kh * (B_SZ * 12);
            float2* q0 = (float2*)&ppk[(b0 + lq)     * 12 + lr * 2];
            float2* q1 = (float2*)&ppk[(b0 + lq + 8) * 12 + lr * 2];
            *q0 = make_float2(acc0[0], acc0[1]);
            *q1 = make_float2(acc0[2], acc0[3]);
        }
        __syncthreads();

        if (tid < 128) {
            const float4 q0 = *(const float4*)&pp[gb * 12 + gjl * 4];
            const float4 q1 = *(const float4*)&pp[B_SZ * 12 + gb * 12 + gjl * 4];
            float p0 = q0.x + q1.x + z.x;
            float p1 = q0.y + q1.y + z.y;
            float p2 = q0.z + q1.z + z.z;
            float p3 = q0.w + q1.w + z.w;

            float f  = 1.f / (1.f + expf(-p0));
            float ig = 1.f / (1.f + expf(-p1));
            float o  = 1.f / (1.f + expf(-p2));
            float g  = tanhf(p3);
            creg = f * creg + ig * g;
            float hn = o * tanhf(creg);

            g_hT[par ^ 1][gjg * B_SZ + gb] = hn;
            size_t off = (size_t)(gb * T_LEN + t) * H_SZ + gjg;
            hseq[off] = hn;
            cseq[off] = creg;
            __threadfence();
        }
        GRIDBAR();
    }
}

// ---------------- launch --------------------------------------------------
extern "C" void kernel_launch(void* const* d_in, const int* in_sizes, int n_in,
                              void* d_out, int out_size) {
    const float* x    = (const float*)d_in[0];   // [B,T,D]
    const float* h0   = (const float*)d_in[1];   // [B,H]
    const float* c0   = (const float*)d_in[2];   // [B,H]
    const float* Win  = (const float*)d_in[3];   // [D,H]
    const float* Wx   = (const float*)d_in[4];   // [4,D,H]
    const float* Wh   = (const float*)d_in[5];   // [4,H,H]
    const float* We   = (const float*)d_in[6];   // [4,H,H]
    const float* bb   = (const float*)d_in[7];   // [4,H]
    const float* Wout = (const float*)d_in[8];   // [H,D]
    const float* bout = (const float*)d_in[9];   // [D]

    float* out  = (float*)d_out;
    float* yhat = out;                                   // [B,T,D]
    float* hseq = out + (size_t)B_SZ * T_LEN * D_SZ;     // [B,T,H]
    float* cseq = hseq + (size_t)B_SZ * T_LEN * H_SZ;    // [B,T,H]

    float *pM2, *pbias2, *pZ;
    cudaGetSymbolAddress((void**)&pM2,    g_M2);
    cudaGetSymbolAddress((void**)&pbias2, g_bias2);
    cudaGetSymbolAddress((void**)&pZ,     g_Z);

    // phase 0: fold weights
    k_prepM<<<dim3(4, 256), 256>>>(Win, Wx, We, bb);
    k_prepW<<<dim3(4, 256), 256>>>(Wh, We);

    // phase A: Z = x * M2 + bias2      (65536 x 1024 x 256)
    k_gemm_bias<64><<<dim3(1024 / 64, 65536 / 128), 256>>>(
        x, pM2, pbias2, pZ, 1024, 256);

    // phase B: serial recurrence (persistent, grid-barriered, tf32 mma)
    const int smemB = (H_SZ * HS_STRIDE + 2 * B_SZ * 12) * 4;   // 79872 B
    cudaFuncSetAttribute(k_recur, cudaFuncAttributeMaxDynamicSharedMemorySize,
                         smemB);
    k_recur<<<NCTA, 256, smemB>>>(h0, c0, hseq, cseq);

    // phase C: y = h_seq * W_out + b_out   (65536 x 256 x 256)
    k_gemm_bias<64><<<dim3(256 / 64, 65536 / 128), 256>>>(
        hseq, Wout, bout, yhat, 256, 256);
}